// round 8
// baseline (speedup 1.0000x reference)
#include <cuda_runtime.h>

#define EPSF 1e-6f
#define TPB 128
#define MAXBLOCKS 4096

__device__ float g_partial[MAXBLOCKS];
__device__ unsigned int g_count = 0;   // atomicInc wraps to 0 -> graph-replay-safe

__device__ __forceinline__ float fast_rcp(float x) {
    float r;
    asm("rcp.approx.f32 %0, %1;" : "=f"(r) : "f"(x));
    return r;
}

// Shared polygon buffers, float2, [slot][tid] layout (conflict-free).
// Buffer A = slots 0..6 (7 slots), buffer B = slots 7..12 (6 slots).
#define NSLOT 13

// One clip stage, forward edge-walk:
//  - batch-load input polygon into registers (MLP across all LDS)
//  - all signed distances computed up front (independent FMA chains)
//  - per edge k: emit vertex k if inside, then crossing if sign change.
// Output is the same cyclic polygon as classic SH (rotated start) -> same area.
template <int MAXIN>
__device__ __forceinline__ int clip_stage(
    float ax, float ay, float ex, float ey,
    const float2* __restrict__ in, int cnt,
    float2* __restrict__ out)
{
    float vx[MAXIN], vy[MAXIN], d[MAXIN];
    #pragma unroll
    for (int k = 0; k < MAXIN; k++) {
        float2 v = (k < cnt) ? in[k * TPB] : make_float2(0.0f, 0.0f);
        vx[k] = v.x; vy[k] = v.y;
    }
    #pragma unroll
    for (int k = 0; k < MAXIN; k++)
        d[k] = ex * (vy[k] - ay) - ey * (vx[k] - ax);

    int oc = 0;
    #pragma unroll
    for (int k = 0; k < MAXIN; k++) {
        if (k < cnt) {
            const int kn = (k + 1 < MAXIN) ? (k + 1) : 0;  // compile-time index
            bool wrap = (k + 1 >= cnt);
            float nx = wrap ? vx[0] : vx[kn];
            float ny = wrap ? vy[0] : vy[kn];
            float dn = wrap ? d[0]  : d[kn];
            bool in_c = (d[k] >= 0.0f);
            bool in_n = (dn   >= 0.0f);
            if (in_c) out[oc * TPB] = make_float2(vx[k], vy[k]);
            int o2 = oc + (in_c ? 1 : 0);
            if (in_c != in_n) {
                float t = d[k] * fast_rcp(d[k] - dn);
                out[o2 * TPB] = make_float2(vx[k] + t * (nx - vx[k]),
                                            vy[k] + t * (ny - vy[k]));
                o2++;
            }
            oc = o2;
        }
    }
    return oc;
}

__global__ __launch_bounds__(TPB)
void poly_iou_kernel(const float* __restrict__ pred,
                     const float* __restrict__ tgt,
                     float* __restrict__ out,
                     int n) {
    __shared__ float2 shbuf[NSLOT * TPB];

    int i = blockIdx.x * blockDim.x + threadIdx.x;
    int tid = threadIdx.x;
    float loss = 0.0f;

    if (i < n) {
        float4 a0 = reinterpret_cast<const float4*>(pred)[2 * i];
        float4 a1 = reinterpret_cast<const float4*>(pred)[2 * i + 1];
        float4 c0 = reinterpret_cast<const float4*>(tgt)[2 * i];
        float4 c1 = reinterpret_cast<const float4*>(tgt)[2 * i + 1];

        float p1x[4] = {a0.x, a0.z, a1.x, a1.z};
        float p1y[4] = {a0.y, a0.w, a1.y, a1.w};
        float p2x[4] = {c0.x, c0.z, c1.x, c1.z};
        float p2y[4] = {c0.y, c0.w, c1.y, c1.w};

        // Shoelace areas (roll(+1) order, as reference).
        float s1 = 0.0f, s2 = 0.0f;
        #pragma unroll
        for (int k = 0; k < 4; k++) {
            int km = (k + 3) & 3;
            s1 += p1x[k] * p1y[km] - p1x[km] * p1y[k];
            s2 += p2x[k] * p2y[km] - p2x[km] * p2y[k];
        }
        float area1 = 0.5f * fabsf(s1);
        float area2 = 0.5f * fabsf(s2);

        // Orientation of poly2 so "inside" is d >= 0.
        float ocr = (p2x[1] - p2x[0]) * (p2y[2] - p2y[1]) -
                    (p2y[1] - p2y[0]) * (p2x[2] - p2x[1]);
        float orient = (ocr >= 0.0f) ? 1.0f : -1.0f;

        float2* pA = &shbuf[tid];            // slots 0..6
        float2* pB = &shbuf[7 * TPB + tid];  // slots 7..12

        // --- Stage 0: quad1 (registers) clipped by edge 0 -> pA (<=5) ---
        int cnt;
        {
            float ax = p2x[0], ay = p2y[0];
            float ex = (p2x[1] - ax) * orient;
            float ey = (p2y[1] - ay) * orient;
            float d0[4];
            #pragma unroll
            for (int k = 0; k < 4; k++)
                d0[k] = ex * (p1y[k] - ay) - ey * (p1x[k] - ax);
            int oc = 0;
            #pragma unroll
            for (int k = 0; k < 4; k++) {
                const int kn = (k + 1) & 3;
                bool in_c = (d0[k]  >= 0.0f);
                bool in_n = (d0[kn] >= 0.0f);
                if (in_c) pA[oc * TPB] = make_float2(p1x[k], p1y[k]);
                int o2 = oc + (in_c ? 1 : 0);
                if (in_c != in_n) {
                    float t = d0[k] * fast_rcp(d0[k] - d0[kn]);
                    pA[o2 * TPB] = make_float2(p1x[k] + t * (p1x[kn] - p1x[k]),
                                               p1y[k] + t * (p1y[kn] - p1y[k]));
                    o2++;
                }
                oc = o2;
            }
            cnt = oc;
        }

        // --- Stage 1: pA (<=5) -> pB (<=6) ---
        {
            float ax = p2x[1], ay = p2y[1];
            float ex = (p2x[2] - ax) * orient;
            float ey = (p2y[2] - ay) * orient;
            cnt = clip_stage<5>(ax, ay, ex, ey, pA, cnt, pB);
        }
        // --- Stage 2: pB (<=6) -> pA (<=7) ---
        {
            float ax = p2x[2], ay = p2y[2];
            float ex = (p2x[3] - ax) * orient;
            float ey = (p2y[3] - ay) * orient;
            cnt = clip_stage<6>(ax, ay, ex, ey, pB, cnt, pA);
        }

        // --- Stage 3: pA (<=7) clipped by edge 3, streamed into shoelace ---
        float s = 0.0f;
        int oc = 0;
        {
            float ax = p2x[3], ay = p2y[3];
            float ex = (p2x[0] - ax) * orient;
            float ey = (p2y[0] - ay) * orient;

            float vx[7], vy[7], d[7];
            #pragma unroll
            for (int k = 0; k < 7; k++) {
                float2 v = (k < cnt) ? pA[k * TPB] : make_float2(0.0f, 0.0f);
                vx[k] = v.x; vy[k] = v.y;
            }
            #pragma unroll
            for (int k = 0; k < 7; k++)
                d[k] = ex * (vy[k] - ay) - ey * (vx[k] - ax);

            float fx = 0.0f, fy = 0.0f, pox = 0.0f, poy = 0.0f;
            #pragma unroll
            for (int k = 0; k < 7; k++) {
                if (k < cnt) {
                    const int kn = (k + 1 < 7) ? (k + 1) : 0;
                    bool wrap = (k + 1 >= cnt);
                    float nx = wrap ? vx[0] : vx[kn];
                    float ny = wrap ? vy[0] : vy[kn];
                    float dn = wrap ? d[0]  : d[kn];
                    bool in_c = (d[k] >= 0.0f);
                    bool in_n = (dn   >= 0.0f);
                    if (in_c) {
                        float X = vx[k], Y = vy[k];
                        s += (oc > 0) ? (pox * Y - poy * X) : 0.0f;
                        fx = (oc == 0) ? X : fx;
                        fy = (oc == 0) ? Y : fy;
                        pox = X; poy = Y; oc++;
                    }
                    if (in_c != in_n) {
                        float t = d[k] * fast_rcp(d[k] - dn);
                        float X = vx[k] + t * (nx - vx[k]);
                        float Y = vy[k] + t * (ny - vy[k]);
                        s += (oc > 0) ? (pox * Y - poy * X) : 0.0f;
                        fx = (oc == 0) ? X : fx;
                        fy = (oc == 0) ? Y : fy;
                        pox = X; poy = Y; oc++;
                    }
                }
            }
            if (oc >= 3) s += pox * fy - poy * fx;   // close polygon
        }
        float overlap = (oc >= 3) ? 0.5f * fabsf(s) : 0.0f;

        float iou = overlap * fast_rcp(area1 + area2 - overlap + EPSF);
        iou = fminf(fmaxf(iou, EPSF), 1.0f);
        loss = 1.0f - iou;
    }

    // --- Intra-block reduction (TPB=128 -> 4 warps) ---
    #pragma unroll
    for (int off = 16; off > 0; off >>= 1)
        loss += __shfl_down_sync(0xffffffffu, loss, off);

    __shared__ float wsum[TPB / 32];
    int lane = threadIdx.x & 31;
    int wid  = threadIdx.x >> 5;
    if (lane == 0) wsum[wid] = loss;
    __syncthreads();

    if (wid == 0) {
        float v = (lane < TPB / 32) ? wsum[lane] : 0.0f;
        #pragma unroll
        for (int off = TPB / 64; off > 0; off >>= 1)
            v += __shfl_down_sync(0xffffffffu, v, off);
        if (lane == 0) wsum[0] = v;
    }
    __syncthreads();

    // --- Last-block-done final reduction (single launch) ---
    __shared__ bool is_last;
    if (threadIdx.x == 0) {
        g_partial[blockIdx.x] = wsum[0];
        __threadfence();
        unsigned prev = atomicInc(&g_count, gridDim.x - 1);
        is_last = (prev == gridDim.x - 1);
    }
    __syncthreads();

    if (is_last) {
        double s = 0.0;
        for (int k = threadIdx.x; k < (int)gridDim.x; k += TPB)
            s += (double)g_partial[k];
        #pragma unroll
        for (int off = 16; off > 0; off >>= 1)
            s += __shfl_down_sync(0xffffffffu, s, off);

        __shared__ double dsum[TPB / 32];
        if (lane == 0) dsum[wid] = s;
        __syncthreads();
        if (wid == 0) {
            double v = (lane < TPB / 32) ? dsum[lane] : 0.0;
            #pragma unroll
            for (int off = TPB / 64; off > 0; off >>= 1)
                v += __shfl_down_sync(0xffffffffu, v, off);
            if (lane == 0)
                out[0] = (float)(v / (double)n);
        }
    }
}

extern "C" void kernel_launch(void* const* d_in, const int* in_sizes, int n_in,
                              void* d_out, int out_size) {
    const float* pred = (const float*)d_in[0];
    const float* tgt  = (const float*)d_in[1];
    int n = in_sizes[0] / 8;

    int blocks = (n + TPB - 1) / TPB;
    poly_iou_kernel<<<blocks, TPB>>>(pred, tgt, (float*)d_out, n);
}

// round 9
// speedup vs baseline: 1.0123x; 1.0123x over previous
#include <cuda_runtime.h>

#define EPSF 1e-6f
#define TPB 128
#define MAXBLOCKS 4096
// Shared slots per thread: bufA = 0..6, bufB = 7..12, dump = 13 (write-only)
#define NSLOT 14

__device__ float g_partial[MAXBLOCKS];
__device__ unsigned int g_count = 0;   // atomicInc wraps to 0 -> graph-replay-safe

__device__ __forceinline__ float fast_rcp(float x) {
    float r;
    asm("rcp.approx.f32 %0, %1;" : "=f"(r) : "f"(x));
    return r;
}

// Branchless clip stage. Input polygon padded by duplicating the last valid
// vertex up to MAXIN slots (read-side index clamp). Duplicate vertices are
// Sutherland-Hodgman-invariant: equal distances -> never a crossing; dup
// emits contribute 0 to the final shoelace. Every edge does two
// unconditional STS; invalid emits go to the per-thread dump slot.
template <int MAXIN>
__device__ __forceinline__ int clip_stage_bl(
    float ax, float ay, float ex, float ey,
    const float2* __restrict__ in, int cnt,
    float2* __restrict__ out, float2* __restrict__ dump)
{
    float vx[MAXIN], vy[MAXIN], d[MAXIN];
    int last = max(cnt - 1, 0);
    #pragma unroll
    for (int k = 0; k < MAXIN; k++) {
        float2 v = in[min(k, last) * TPB];
        vx[k] = v.x; vy[k] = v.y;
    }
    #pragma unroll
    for (int k = 0; k < MAXIN; k++)
        d[k] = ex * (vy[k] - ay) - ey * (vx[k] - ax);

    int oc = 0;
    #pragma unroll
    for (int k = 0; k < MAXIN; k++) {
        const int kn = (k + 1) % MAXIN;        // compile-time
        bool in_c  = (d[k]  >= 0.0f);
        bool in_n  = (d[kn] >= 0.0f);
        bool cross = (in_c != in_n);

        float2* dst0 = in_c ? (out + oc * TPB) : dump;
        *dst0 = make_float2(vx[k], vy[k]);
        int o2 = oc + (in_c ? 1 : 0);

        float t = d[k] * fast_rcp(d[k] - d[kn]);
        float X = fmaf(t, vx[kn] - vx[k], vx[k]);
        float Y = fmaf(t, vy[kn] - vy[k], vy[k]);
        float2* dst1 = cross ? (out + o2 * TPB) : dump;
        *dst1 = make_float2(X, Y);
        oc = o2 + (cross ? 1 : 0);
    }
    return oc;
}

__global__ __launch_bounds__(TPB)
void poly_iou_kernel(const float* __restrict__ pred,
                     const float* __restrict__ tgt,
                     float* __restrict__ out,
                     int n) {
    __shared__ float2 shbuf[NSLOT * TPB];

    int i = blockIdx.x * blockDim.x + threadIdx.x;
    int tid = threadIdx.x;
    float loss = 0.0f;

    if (i < n) {
        float4 a0 = reinterpret_cast<const float4*>(pred)[2 * i];
        float4 a1 = reinterpret_cast<const float4*>(pred)[2 * i + 1];
        float4 c0 = reinterpret_cast<const float4*>(tgt)[2 * i];
        float4 c1 = reinterpret_cast<const float4*>(tgt)[2 * i + 1];

        float p1x[4] = {a0.x, a0.z, a1.x, a1.z};
        float p1y[4] = {a0.y, a0.w, a1.y, a1.w};
        float p2x[4] = {c0.x, c0.z, c1.x, c1.z};
        float p2y[4] = {c0.y, c0.w, c1.y, c1.w};

        // Shoelace areas (roll(+1) order, as reference).
        float s1 = 0.0f, s2 = 0.0f;
        #pragma unroll
        for (int k = 0; k < 4; k++) {
            int km = (k + 3) & 3;
            s1 += p1x[k] * p1y[km] - p1x[km] * p1y[k];
            s2 += p2x[k] * p2y[km] - p2x[km] * p2y[k];
        }
        float area1 = 0.5f * fabsf(s1);
        float area2 = 0.5f * fabsf(s2);

        // Orientation of poly2 so "inside" is d >= 0.
        float ocr = (p2x[1] - p2x[0]) * (p2y[2] - p2y[1]) -
                    (p2y[1] - p2y[0]) * (p2x[2] - p2x[1]);
        float orient = (ocr >= 0.0f) ? 1.0f : -1.0f;

        float2* pA   = &shbuf[tid];             // slots 0..6
        float2* pB   = &shbuf[7 * TPB + tid];   // slots 7..12
        float2* dump = &shbuf[13 * TPB + tid];  // write-only

        // Zero-init buffers (per-thread columns; no sync needed).
        #pragma unroll
        for (int k = 0; k < 13; k++)
            shbuf[k * TPB + tid] = make_float2(0.0f, 0.0f);

        // --- Stage 0: quad1 (registers, cnt=4 exact) by edge 0 -> pA (<=5) ---
        int cnt;
        {
            float ax = p2x[0], ay = p2y[0];
            float ex = (p2x[1] - ax) * orient;
            float ey = (p2y[1] - ay) * orient;
            float d0[4];
            #pragma unroll
            for (int k = 0; k < 4; k++)
                d0[k] = ex * (p1y[k] - ay) - ey * (p1x[k] - ax);
            int oc = 0;
            #pragma unroll
            for (int k = 0; k < 4; k++) {
                const int kn = (k + 1) & 3;
                bool in_c  = (d0[k]  >= 0.0f);
                bool in_n  = (d0[kn] >= 0.0f);
                bool cross = (in_c != in_n);

                float2* dst0 = in_c ? (pA + oc * TPB) : dump;
                *dst0 = make_float2(p1x[k], p1y[k]);
                int o2 = oc + (in_c ? 1 : 0);

                float t = d0[k] * fast_rcp(d0[k] - d0[kn]);
                float X = fmaf(t, p1x[kn] - p1x[k], p1x[k]);
                float Y = fmaf(t, p1y[kn] - p1y[k], p1y[k]);
                float2* dst1 = cross ? (pA + o2 * TPB) : dump;
                *dst1 = make_float2(X, Y);
                oc = o2 + (cross ? 1 : 0);
            }
            cnt = oc;
        }
        bool valid = (cnt > 0);

        // --- Stage 1: pA (<=5) -> pB (<=6) ---
        {
            float ax = p2x[1], ay = p2y[1];
            float ex = (p2x[2] - ax) * orient;
            float ey = (p2y[2] - ay) * orient;
            cnt = clip_stage_bl<5>(ax, ay, ex, ey, pA, cnt, pB, dump);
        }
        valid = valid && (cnt > 0);

        // --- Stage 2: pB (<=6) -> pA (<=7) ---
        {
            float ax = p2x[2], ay = p2y[2];
            float ex = (p2x[3] - ax) * orient;
            float ey = (p2y[3] - ay) * orient;
            cnt = clip_stage_bl<6>(ax, ay, ex, ey, pB, cnt, pA, dump);
        }
        valid = valid && (cnt > 0);

        // --- Stage 3: pA (<=7) by edge 3, streamed into shoelace (branchless) ---
        float s = 0.0f;
        int oc = 0;
        {
            float ax = p2x[3], ay = p2y[3];
            float ex = (p2x[0] - ax) * orient;
            float ey = (p2y[0] - ay) * orient;

            float vx[7], vy[7], d[7];
            int last = max(cnt - 1, 0);
            #pragma unroll
            for (int k = 0; k < 7; k++) {
                float2 v = pA[min(k, last) * TPB];
                vx[k] = v.x; vy[k] = v.y;
            }
            #pragma unroll
            for (int k = 0; k < 7; k++)
                d[k] = ex * (vy[k] - ay) - ey * (vx[k] - ax);

            float fx = 0.0f, fy = 0.0f, pox = 0.0f, poy = 0.0f;
            #pragma unroll
            for (int k = 0; k < 7; k++) {
                const int kn = (k + 1) % 7;
                bool in_c  = (d[k]  >= 0.0f);
                bool in_n  = (d[kn] >= 0.0f);
                bool cross = (in_c != in_n);

                // vertex emit
                {
                    float X = vx[k], Y = vy[k];
                    bool first = in_c && (oc == 0);
                    s  += (in_c && oc > 0) ? (pox * Y - poy * X) : 0.0f;
                    fx  = first ? X : fx;
                    fy  = first ? Y : fy;
                    pox = in_c ? X : pox;
                    poy = in_c ? Y : poy;
                    oc += (in_c ? 1 : 0);
                }
                // crossing emit
                {
                    float t = d[k] * fast_rcp(d[k] - d[kn]);
                    float X = fmaf(t, vx[kn] - vx[k], vx[k]);
                    float Y = fmaf(t, vy[kn] - vy[k], vy[k]);
                    bool first = cross && (oc == 0);
                    s  += (cross && oc > 0) ? (pox * Y - poy * X) : 0.0f;
                    fx  = first ? X : fx;
                    fy  = first ? Y : fy;
                    pox = cross ? X : pox;
                    poy = cross ? Y : poy;
                    oc += (cross ? 1 : 0);
                }
            }
            s += (oc >= 3) ? (pox * fy - poy * fx) : 0.0f;  // close polygon
        }
        float overlap = (valid && oc >= 3) ? 0.5f * fabsf(s) : 0.0f;

        float iou = overlap * fast_rcp(area1 + area2 - overlap + EPSF);
        iou = fminf(fmaxf(iou, EPSF), 1.0f);
        loss = 1.0f - iou;
    }

    // --- Intra-block reduction (TPB=128 -> 4 warps) ---
    #pragma unroll
    for (int off = 16; off > 0; off >>= 1)
        loss += __shfl_down_sync(0xffffffffu, loss, off);

    __shared__ float wsum[TPB / 32];
    int lane = threadIdx.x & 31;
    int wid  = threadIdx.x >> 5;
    if (lane == 0) wsum[wid] = loss;
    __syncthreads();

    if (wid == 0) {
        float v = (lane < TPB / 32) ? wsum[lane] : 0.0f;
        #pragma unroll
        for (int off = TPB / 64; off > 0; off >>= 1)
            v += __shfl_down_sync(0xffffffffu, v, off);
        if (lane == 0) wsum[0] = v;
    }
    __syncthreads();

    // --- Last-block-done final reduction (single launch) ---
    __shared__ bool is_last;
    if (threadIdx.x == 0) {
        g_partial[blockIdx.x] = wsum[0];
        __threadfence();
        unsigned prev = atomicInc(&g_count, gridDim.x - 1);
        is_last = (prev == gridDim.x - 1);
    }
    __syncthreads();

    if (is_last) {
        double sd = 0.0;
        for (int k = threadIdx.x; k < (int)gridDim.x; k += TPB)
            sd += (double)g_partial[k];
        #pragma unroll
        for (int off = 16; off > 0; off >>= 1)
            sd += __shfl_down_sync(0xffffffffu, sd, off);

        __shared__ double dsum[TPB / 32];
        if (lane == 0) dsum[wid] = sd;
        __syncthreads();
        if (wid == 0) {
            double v = (lane < TPB / 32) ? dsum[lane] : 0.0;
            #pragma unroll
            for (int off = TPB / 64; off > 0; off >>= 1)
                v += __shfl_down_sync(0xffffffffu, v, off);
            if (lane == 0)
                out[0] = (float)(v / (double)n);
        }
    }
}

extern "C" void kernel_launch(void* const* d_in, const int* in_sizes, int n_in,
                              void* d_out, int out_size) {
    const float* pred = (const float*)d_in[0];
    const float* tgt  = (const float*)d_in[1];
    int n = in_sizes[0] / 8;

    int blocks = (n + TPB - 1) / TPB;
    poly_iou_kernel<<<blocks, TPB>>>(pred, tgt, (float*)d_out, n);
}